// round 2
// baseline (speedup 1.0000x reference)
#include <cuda_runtime.h>
#include <cuda_bf16.h>
#include <math.h>

// ---------------------------------------------------------------------------
// Problem constants
// ---------------------------------------------------------------------------
#define T_MAX 4096
#define H_DIM 2048
#define OUT_DIM 10
#define NCTA 148
#define SCAN_THREADS 512
#define EPS 1e-6f

// scratch (device globals: allocation-free)
__device__ float g_xf[T_MAX * H_DIM];   // x @ W_f + b_f
__device__ float g_xh[T_MAX * H_DIM];   // x @ W_h + b_h
__device__ float g_h [T_MAX * H_DIM];   // scan output
__device__ float g_hn[T_MAX * H_DIM];   // layernorm output (layer 0)
__device__ int   g_ctr[T_MAX];          // per-step barrier counters

// ---------------------------------------------------------------------------
// SGEMM with bias:  C[M,N] = A[M,K] @ B[K,N] + bias[N]   (all row-major fp32)
// 128x128 tile, BK=8, 256 threads, 8x8 per-thread microtile.
// ---------------------------------------------------------------------------
#define BM 128
#define BN 128
#define BK 8
#define TM 8
#define TN 8

__global__ __launch_bounds__(256) void sgemm_bias_kernel(
    const float* __restrict__ A, const float* __restrict__ B,
    const float* __restrict__ bias, float* __restrict__ C,
    int M, int N, int K)
{
    __shared__ float As[BK][BM];
    __shared__ float Bs[BK][BN];

    const int bx = blockIdx.x;   // N tile
    const int by = blockIdx.y;   // M tile
    const int tid = threadIdx.x;

    const int aRow = tid >> 1;          // 0..127
    const int aCol = (tid & 1) * 4;     // 0 or 4
    const int bRow = tid >> 5;          // 0..7
    const int bCol = (tid & 31) * 4;    // 0..124

    const int tRow = (tid >> 4) * TM;   // 0..120
    const int tCol = (tid & 15) * TN;   // 0..120

    const float* Aptr = A + (size_t)(by * BM) * K;
    const float* Bptr = B + bx * BN;

    float acc[TM][TN];
    #pragma unroll
    for (int i = 0; i < TM; i++)
        #pragma unroll
        for (int j = 0; j < TN; j++) acc[i][j] = 0.f;

    for (int k0 = 0; k0 < K; k0 += BK) {
        float4 av = *(const float4*)(Aptr + (size_t)aRow * K + k0 + aCol);
        As[aCol + 0][aRow] = av.x;
        As[aCol + 1][aRow] = av.y;
        As[aCol + 2][aRow] = av.z;
        As[aCol + 3][aRow] = av.w;
        float4 bv = *(const float4*)(Bptr + (size_t)(k0 + bRow) * N + bCol);
        *(float4*)&Bs[bRow][bCol] = bv;
        __syncthreads();

        #pragma unroll
        for (int kk = 0; kk < BK; kk++) {
            float4 a0 = *(const float4*)&As[kk][tRow];
            float4 a1 = *(const float4*)&As[kk][tRow + 4];
            float4 b0 = *(const float4*)&Bs[kk][tCol];
            float4 b1 = *(const float4*)&Bs[kk][tCol + 4];
            float ar[8] = {a0.x, a0.y, a0.z, a0.w, a1.x, a1.y, a1.z, a1.w};
            float br[8] = {b0.x, b0.y, b0.z, b0.w, b1.x, b1.y, b1.z, b1.w};
            #pragma unroll
            for (int i = 0; i < TM; i++)
                #pragma unroll
                for (int j = 0; j < TN; j++)
                    acc[i][j] = fmaf(ar[i], br[j], acc[i][j]);
        }
        __syncthreads();
    }

    #pragma unroll
    for (int i = 0; i < TM; i++) {
        const int r = by * BM + tRow + i;
        #pragma unroll
        for (int j = 0; j < TN; j += 4) {
            const int c = bx * BN + tCol + j;
            float4 v;
            v.x = acc[i][j + 0] + bias[c + 0];
            v.y = acc[i][j + 1] + bias[c + 1];
            v.z = acc[i][j + 2] + bias[c + 2];
            v.w = acc[i][j + 3] + bias[c + 3];
            *(float4*)(C + (size_t)r * N + c) = v;
        }
    }
}

// ---------------------------------------------------------------------------
// Persistent JANET scan. 148 CTAs x 512 threads, single wave guaranteed
// (229.5 KB dyn smem -> 1 CTA/SM). CTA b owns column pairs [c0, c1).
// smem holds fp32 columns of U_f then U_h for those columns:
//   wbuf[d*H + k],  d in [0, np) -> U_f col (c0+d),  d in [np, 2np) -> U_h.
// ---------------------------------------------------------------------------
__global__ __launch_bounds__(SCAN_THREADS, 1) void janet_scan_kernel(
    const float* __restrict__ Uf, const float* __restrict__ Uh,
    const float* __restrict__ xf, const float* __restrict__ xh,
    float* __restrict__ Hout, const float* __restrict__ prelu_a,
    int* __restrict__ ctr, int T)
{
    extern __shared__ float smem[];
    const int H = H_DIM;
    const int b = blockIdx.x;
    const int c0 = (b * H) / NCTA;
    const int c1 = ((b + 1) * H) / NCTA;
    const int np = c1 - c0;          // 13 or 14 column pairs
    const int nd = 2 * np;           // dot products per step

    float* wbuf = smem;              // nd * H floats
    float* dots = smem + nd * H;     // nd floats

    const int tid  = threadIdx.x;
    const int lane = tid & 31;
    const int warp = tid >> 5;
    const float a = *prelu_a;

    // ---- load weights into smem (reasonably coalesced: 32 cols per row seg) ----
    for (int idx = tid; idx < 32 * H; idx += SCAN_THREADS) {
        const int cl = idx & 31;
        const int k  = idx >> 5;
        if (cl < np) {
            wbuf[cl * H + k]        = Uf[(size_t)k * H + c0 + cl];
            wbuf[(np + cl) * H + k] = Uh[(size_t)k * H + c0 + cl];
        }
    }
    __syncthreads();

    // warp -> dot assignment (each warp: 1 or 2 dots, reuses its h registers)
    const int dstart = (warp * nd) >> 4;
    const int dend   = ((warp + 1) * nd) >> 4;

    // per-column-pair thread state (tid < np)
    float hprev = 0.f;
    float xf_c = 0.f, xh_c = 0.f;
    const int myc = c0 + tid;
    if (tid < np) {
        xf_c = xf[myc];
        xh_c = xh[myc];
    }

    for (int t = 0; t < T; t++) {
        // ---- load h_{t-1} (full row per warp) into registers ----
        float4 hreg[16];
        if (t == 0) {
            #pragma unroll
            for (int j = 0; j < 16; j++) hreg[j] = make_float4(0.f, 0.f, 0.f, 0.f);
        } else {
            const float4* hv = (const float4*)(Hout + (size_t)(t - 1) * H);
            #pragma unroll
            for (int j = 0; j < 16; j++)
                hreg[j] = __ldcg(&hv[j * 32 + lane]);   // L2, skip L1
        }

        // ---- dot products from smem weights ----
        for (int d = dstart; d < dend; d++) {
            const float4* w4 = (const float4*)(wbuf + d * H);
            float acc = 0.f;
            #pragma unroll
            for (int j = 0; j < 16; j++) {
                float4 wv = w4[j * 32 + lane];
                acc = fmaf(hreg[j].x, wv.x, acc);
                acc = fmaf(hreg[j].y, wv.y, acc);
                acc = fmaf(hreg[j].z, wv.z, acc);
                acc = fmaf(hreg[j].w, wv.w, acc);
            }
            acc += __shfl_xor_sync(0xffffffffu, acc, 16);
            acc += __shfl_xor_sync(0xffffffffu, acc, 8);
            acc += __shfl_xor_sync(0xffffffffu, acc, 4);
            acc += __shfl_xor_sync(0xffffffffu, acc, 2);
            acc += __shfl_xor_sync(0xffffffffu, acc, 1);
            if (lane == 0) dots[d] = acc;
        }
        __syncthreads();

        // ---- gate combine, PReLU, write h_t slice ----
        if (tid < np) {
            const float pf = dots[tid] + xf_c;
            const float ph = dots[np + tid] + xh_c;
            const float f  = 1.f / (1.f + __expf(-pf));
            const float cd = tanhf(ph);
            float hn = f * hprev + (1.f - f) * cd;
            hn = (hn >= 0.f) ? hn : a * hn;
            Hout[(size_t)t * H + myc] = hn;
            hprev = hn;
            if (t + 1 < T) {   // prefetch next step's input projections
                xf_c = xf[(size_t)(t + 1) * H + myc];
                xh_c = xh[(size_t)(t + 1) * H + myc];
            }
            __threadfence();   // make h_t slice visible device-wide
        }
        __syncthreads();       // dots consumed; all writers fenced

        // ---- grid-wide barrier on step t ----
        if (tid == 0) {
            atomicAdd(&ctr[t], 1);
            volatile int* p = ctr + t;
            while (*p < NCTA) { }
            __threadfence();
        }
        __syncthreads();
    }
}

// ---------------------------------------------------------------------------
// block reduce helper (256 threads)
// ---------------------------------------------------------------------------
__device__ __forceinline__ float block_sum_256(float v) {
    __shared__ float sh[8];
    const int tid = threadIdx.x;
    #pragma unroll
    for (int s = 16; s; s >>= 1) v += __shfl_xor_sync(0xffffffffu, v, s);
    if ((tid & 31) == 0) sh[tid >> 5] = v;
    __syncthreads();
    if (tid == 0) {
        float r = 0.f;
        #pragma unroll
        for (int i = 0; i < 8; i++) r += sh[i];
        sh[0] = r;
    }
    __syncthreads();
    const float r = sh[0];
    __syncthreads();
    return r;
}

// ---------------------------------------------------------------------------
// LayerNorm (torch-style: unbiased std, y = g*(x-m)/(s+eps) + b). 1 row/block.
// ---------------------------------------------------------------------------
__global__ __launch_bounds__(256) void layernorm_kernel(
    const float* __restrict__ X, const float* __restrict__ ga,
    const float* __restrict__ be, float* __restrict__ Y)
{
    const int H = H_DIM;
    const int row = blockIdx.x;
    const int tid = threadIdx.x;
    const float* x = X + (size_t)row * H;
    float xr[8];
    #pragma unroll
    for (int j = 0; j < 8; j++) xr[j] = x[tid + 256 * j];

    float s = 0.f;
    #pragma unroll
    for (int j = 0; j < 8; j++) s += xr[j];
    const float mean = block_sum_256(s) * (1.f / H);

    float sq = 0.f;
    #pragma unroll
    for (int j = 0; j < 8; j++) { const float d = xr[j] - mean; sq += d * d; }
    const float var = block_sum_256(sq) * (1.f / (H - 1));
    const float inv = 1.f / (sqrtf(var) + EPS);

    float* y = Y + (size_t)row * H;
    #pragma unroll
    for (int j = 0; j < 8; j++) {
        const int k = tid + 256 * j;
        y[k] = ga[k] * (xr[j] - mean) * inv + be[k];
    }
}

// ---------------------------------------------------------------------------
// Fused head: LN(layer1 h) @ W_out + b_out -> log_softmax.  1 row/block.
// ---------------------------------------------------------------------------
__global__ __launch_bounds__(256) void head_kernel(
    const float* __restrict__ Hin, const float* __restrict__ ga,
    const float* __restrict__ be, const float* __restrict__ Wout,
    const float* __restrict__ bout, float* __restrict__ out)
{
    const int H = H_DIM;
    const int row = blockIdx.x;
    const int tid = threadIdx.x;
    const float* x = Hin + (size_t)row * H;

    float xr[8];
    #pragma unroll
    for (int j = 0; j < 8; j++) xr[j] = x[tid + 256 * j];

    float s = 0.f;
    #pragma unroll
    for (int j = 0; j < 8; j++) s += xr[j];
    const float mean = block_sum_256(s) * (1.f / H);

    float sq = 0.f;
    #pragma unroll
    for (int j = 0; j < 8; j++) { const float d = xr[j] - mean; sq += d * d; }
    const float var = block_sum_256(sq) * (1.f / (H - 1));
    const float inv = 1.f / (sqrtf(var) + EPS);

    float acc[OUT_DIM];
    #pragma unroll
    for (int o = 0; o < OUT_DIM; o++) acc[o] = 0.f;
    #pragma unroll
    for (int j = 0; j < 8; j++) {
        const int k = tid + 256 * j;
        const float xn = ga[k] * (xr[j] - mean) * inv + be[k];
        #pragma unroll
        for (int o = 0; o < OUT_DIM; o++)
            acc[o] = fmaf(xn, Wout[k * OUT_DIM + o], acc[o]);
    }

    __shared__ float wred[8][OUT_DIM];
    #pragma unroll
    for (int o = 0; o < OUT_DIM; o++) {
        float v = acc[o];
        #pragma unroll
        for (int st = 16; st; st >>= 1) v += __shfl_xor_sync(0xffffffffu, v, st);
        if ((tid & 31) == 0) wred[tid >> 5][o] = v;
    }
    __syncthreads();
    if (tid == 0) {
        float logits[OUT_DIM];
        #pragma unroll
        for (int o = 0; o < OUT_DIM; o++) {
            float v = bout[o];
            #pragma unroll
            for (int w = 0; w < 8; w++) v += wred[w][o];
            logits[o] = v;
        }
        float mx = logits[0];
        #pragma unroll
        for (int o = 1; o < OUT_DIM; o++) mx = fmaxf(mx, logits[o]);
        float se = 0.f;
        #pragma unroll
        for (int o = 0; o < OUT_DIM; o++) se += expf(logits[o] - mx);
        const float lse = mx + logf(se);
        #pragma unroll
        for (int o = 0; o < OUT_DIM; o++)
            out[(size_t)row * OUT_DIM + o] = logits[o] - lse;
    }
}

// ---------------------------------------------------------------------------
// Launch
// ---------------------------------------------------------------------------
extern "C" void kernel_launch(void* const* d_in, const int* in_sizes, int n_in,
                              void* d_out, int out_size)
{
    const float* x     = (const float*)d_in[0];
    const float* W_f0  = (const float*)d_in[1];
    const float* U_f0  = (const float*)d_in[2];
    const float* b_f0  = (const float*)d_in[3];
    const float* W_h0  = (const float*)d_in[4];
    const float* U_h0  = (const float*)d_in[5];
    const float* b_h0  = (const float*)d_in[6];
    const float* pr0   = (const float*)d_in[7];
    const float* ga0   = (const float*)d_in[8];
    const float* be0   = (const float*)d_in[9];
    const float* W_f1  = (const float*)d_in[10];
    const float* U_f1  = (const float*)d_in[11];
    const float* b_f1  = (const float*)d_in[12];
    const float* W_h1  = (const float*)d_in[13];
    const float* U_h1  = (const float*)d_in[14];
    const float* b_h1  = (const float*)d_in[15];
    const float* pr1   = (const float*)d_in[16];
    const float* ga1   = (const float*)d_in[17];
    const float* be1   = (const float*)d_in[18];
    const float* W_out = (const float*)d_in[19];
    const float* b_out = (const float*)d_in[20];
    float* out = (float*)d_out;

    const int H = H_DIM;
    const int T = in_sizes[0] / H;   // 4096

    float *p_xf, *p_xh, *p_h, *p_hn;
    int* p_ctr;
    cudaGetSymbolAddress((void**)&p_xf, g_xf);
    cudaGetSymbolAddress((void**)&p_xh, g_xh);
    cudaGetSymbolAddress((void**)&p_h,  g_h);
    cudaGetSymbolAddress((void**)&p_hn, g_hn);
    cudaGetSymbolAddress((void**)&p_ctr, g_ctr);

    // max pairs per CTA = ceil(2048/148) = 14 -> 28 dots
    const int scan_smem = 28 * H * (int)sizeof(float) + 32 * (int)sizeof(float);
    cudaFuncSetAttribute(janet_scan_kernel,
                         cudaFuncAttributeMaxDynamicSharedMemorySize, scan_smem);

    dim3 ggrid(H / BN, T / BM);   // (16, 32)

    // ---- layer 0 ----
    cudaMemsetAsync(p_ctr, 0, T * sizeof(int));
    sgemm_bias_kernel<<<ggrid, 256>>>(x, W_f0, b_f0, p_xf, T, H, H);
    sgemm_bias_kernel<<<ggrid, 256>>>(x, W_h0, b_h0, p_xh, T, H, H);
    janet_scan_kernel<<<NCTA, SCAN_THREADS, scan_smem>>>(
        U_f0, U_h0, p_xf, p_xh, p_h, pr0, p_ctr, T);
    layernorm_kernel<<<T, 256>>>(p_h, ga0, be0, p_hn);

    // ---- layer 1 ----
    cudaMemsetAsync(p_ctr, 0, T * sizeof(int));
    sgemm_bias_kernel<<<ggrid, 256>>>(p_hn, W_f1, b_f1, p_xf, T, H, H);
    sgemm_bias_kernel<<<ggrid, 256>>>(p_hn, W_h1, b_h1, p_xh, T, H, H);
    janet_scan_kernel<<<NCTA, SCAN_THREADS, scan_smem>>>(
        U_f1, U_h1, p_xf, p_xh, p_h, pr1, p_ctr, T);

    // ---- LN1 + head + log_softmax ----
    head_kernel<<<T, 256>>>(p_h, ga1, be1, W_out, b_out, out);
}

// round 3
// speedup vs baseline: 1.7092x; 1.7092x over previous
#include <cuda_runtime.h>
#include <cuda_bf16.h>
#include <math.h>

// ---------------------------------------------------------------------------
// Problem constants
// ---------------------------------------------------------------------------
#define T_MAX 4096
#define H_DIM 2048
#define OUT_DIM 10
#define NCTA 148
#define SCAN_THREADS 512
#define EPS 1e-6f

// scratch (device globals: allocation-free)
__device__ float g_xf[T_MAX * H_DIM];   // x @ W_f + b_f
__device__ float g_xh[T_MAX * H_DIM];   // x @ W_h + b_h
__device__ float g_h [T_MAX * H_DIM];   // scan output
__device__ float g_hn[T_MAX * H_DIM];   // layernorm output (layer 0)
__device__ int   g_ctr[T_MAX];          // per-step barrier counters

// ---------------------------------------------------------------------------
// SGEMM with bias, fused pair:  C{f,h}[M,N] = A[M,K] @ B{f,h}[K,N] + bias{f,h}
// z-dim selects the f/h problem. 128x128 tile, BK=8, 256 threads, 8x8 micro.
// ---------------------------------------------------------------------------
#define BM 128
#define BN 128
#define BK 8
#define TM 8
#define TN 8

__global__ __launch_bounds__(256) void sgemm_bias2_kernel(
    const float* __restrict__ A,
    const float* __restrict__ Bf, const float* __restrict__ biasf, float* __restrict__ Cf,
    const float* __restrict__ Bh, const float* __restrict__ biash, float* __restrict__ Ch,
    int M, int N, int K)
{
    __shared__ float As[BK][BM];
    __shared__ float Bs[BK][BN];

    const float* B    = (blockIdx.z == 0) ? Bf : Bh;
    const float* bias = (blockIdx.z == 0) ? biasf : biash;
    float*       C    = (blockIdx.z == 0) ? Cf : Ch;

    const int bx = blockIdx.x;   // N tile
    const int by = blockIdx.y;   // M tile
    const int tid = threadIdx.x;

    const int aRow = tid >> 1;          // 0..127
    const int aCol = (tid & 1) * 4;     // 0 or 4
    const int bRow = tid >> 5;          // 0..7
    const int bCol = (tid & 31) * 4;    // 0..124

    const int tRow = (tid >> 4) * TM;   // 0..120
    const int tCol = (tid & 15) * TN;   // 0..120

    const float* Aptr = A + (size_t)(by * BM) * K;
    const float* Bptr = B + bx * BN;

    float acc[TM][TN];
    #pragma unroll
    for (int i = 0; i < TM; i++)
        #pragma unroll
        for (int j = 0; j < TN; j++) acc[i][j] = 0.f;

    for (int k0 = 0; k0 < K; k0 += BK) {
        float4 av = *(const float4*)(Aptr + (size_t)aRow * K + k0 + aCol);
        As[aCol + 0][aRow] = av.x;
        As[aCol + 1][aRow] = av.y;
        As[aCol + 2][aRow] = av.z;
        As[aCol + 3][aRow] = av.w;
        float4 bv = *(const float4*)(Bptr + (size_t)(k0 + bRow) * N + bCol);
        *(float4*)&Bs[bRow][bCol] = bv;
        __syncthreads();

        #pragma unroll
        for (int kk = 0; kk < BK; kk++) {
            float4 a0 = *(const float4*)&As[kk][tRow];
            float4 a1 = *(const float4*)&As[kk][tRow + 4];
            float4 b0 = *(const float4*)&Bs[kk][tCol];
            float4 b1 = *(const float4*)&Bs[kk][tCol + 4];
            float ar[8] = {a0.x, a0.y, a0.z, a0.w, a1.x, a1.y, a1.z, a1.w};
            float br[8] = {b0.x, b0.y, b0.z, b0.w, b1.x, b1.y, b1.z, b1.w};
            #pragma unroll
            for (int i = 0; i < TM; i++)
                #pragma unroll
                for (int j = 0; j < TN; j++)
                    acc[i][j] = fmaf(ar[i], br[j], acc[i][j]);
        }
        __syncthreads();
    }

    #pragma unroll
    for (int i = 0; i < TM; i++) {
        const int r = by * BM + tRow + i;
        #pragma unroll
        for (int j = 0; j < TN; j += 4) {
            const int c = bx * BN + tCol + j;
            float4 v;
            v.x = acc[i][j + 0] + bias[c + 0];
            v.y = acc[i][j + 1] + bias[c + 1];
            v.z = acc[i][j + 2] + bias[c + 2];
            v.w = acc[i][j + 3] + bias[c + 3];
            *(float4*)(C + (size_t)r * N + c) = v;
        }
    }
}

// ---------------------------------------------------------------------------
// Persistent JANET scan, registers-resident weights.
// 148 CTAs x 512 threads (16 warps). CTA b owns column pairs [c0, c1), np<=14.
// dot d (d<np: U_f col c0+d; np<=d<2np: U_h col c0+d-np).
// warp w <-> K-chunk [128w, 128w+128); lane <-> dot.
// Lane holds k-chunk weights: first 64 in REGISTERS, last 64 in smem
// (layout ws[warp][k_local][lane], conflict-free LDS.32).
// h_{t-1} staged once into smem, consumed as float4 broadcasts.
// ---------------------------------------------------------------------------
__global__ __launch_bounds__(SCAN_THREADS, 1) void janet_scan_kernel(
    const float* __restrict__ Uf, const float* __restrict__ Uh,
    const float* __restrict__ xf, const float* __restrict__ xh,
    float* __restrict__ Hout, const float* __restrict__ prelu_a,
    int* __restrict__ ctr, int T)
{
    extern __shared__ float smem[];
    const int H = H_DIM;
    float* ws   = smem;                       // 16*64*32 = 32768 floats (128KB)
    float* hsm  = smem + 16 * 64 * 32;        // 2048 floats (8KB)
    float* part = hsm + H;                    // 16*32 floats (2KB)

    const int b = blockIdx.x;
    const int c0 = (b * H) / NCTA;
    const int c1 = ((b + 1) * H) / NCTA;
    const int np = c1 - c0;          // 13 or 14 column pairs
    const int nd = 2 * np;

    const int tid  = threadIdx.x;
    const int lane = tid & 31;
    const int warp = tid >> 5;
    const float a = *prelu_a;

    // ---- load this lane's weights: 64 regs + 64 smem ----
    const bool valid = lane < nd;
    const int col = c0 + (lane < np ? lane : (valid ? lane - np : 0));
    const float* U = (lane < np) ? Uf : Uh;
    const int kbase = warp * 128;

    float wreg[64];
    #pragma unroll
    for (int i = 0; i < 64; i++)
        wreg[i] = valid ? U[(size_t)(kbase + i) * H + col] : 0.f;
    {
        float* wsp = ws + warp * (64 * 32) + lane;
        #pragma unroll
        for (int i = 0; i < 64; i++)
            wsp[i * 32] = valid ? U[(size_t)(kbase + 64 + i) * H + col] : 0.f;
    }

    // per-dot thread state (warp 0, lane < np drives the gate math)
    float hprev = 0.f, xf_c = 0.f, xh_c = 0.f;
    const int myc = c0 + lane;
    if (warp == 0 && lane < np) {
        xf_c = __ldg(&xf[myc]);
        xh_c = __ldg(&xh[myc]);
    }
    __syncthreads();

    float4* hsm4 = (float4*)hsm;
    const float* wsp = ws + warp * (64 * 32) + lane;

    for (int t = 0; t < T; t++) {
        // ---- stage h_{t-1} into smem (one cooperative 8KB load) ----
        if (t == 0) {
            hsm4[tid] = make_float4(0.f, 0.f, 0.f, 0.f);
        } else {
            hsm4[tid] = __ldcg(((const float4*)(Hout + (size_t)(t - 1) * H)) + tid);
        }
        __syncthreads();

        // ---- partial dot over this warp's k-chunk ----
        const float4* h4 = hsm4 + warp * 32;
        float acc = 0.f;
        #pragma unroll
        for (int j = 0; j < 16; j++) {      // register half
            float4 hv = h4[j];
            acc = fmaf(hv.x, wreg[4 * j + 0], acc);
            acc = fmaf(hv.y, wreg[4 * j + 1], acc);
            acc = fmaf(hv.z, wreg[4 * j + 2], acc);
            acc = fmaf(hv.w, wreg[4 * j + 3], acc);
        }
        #pragma unroll
        for (int j = 0; j < 16; j++) {      // smem half
            float4 hv = h4[16 + j];
            acc = fmaf(hv.x, wsp[(4 * j + 0) * 32], acc);
            acc = fmaf(hv.y, wsp[(4 * j + 1) * 32], acc);
            acc = fmaf(hv.z, wsp[(4 * j + 2) * 32], acc);
            acc = fmaf(hv.w, wsp[(4 * j + 3) * 32], acc);
        }
        part[warp * 32 + lane] = acc;
        __syncthreads();

        // ---- warp 0: reduce partials, gate, publish, grid barrier ----
        if (warp == 0) {
            float s = 0.f;
            #pragma unroll
            for (int w = 0; w < 16; w++) s += part[w * 32 + lane];
            const float partner = __shfl_sync(0xffffffffu, s, lane + np);
            if (lane < np) {
                const float pf = s + xf_c;
                const float ph = partner + xh_c;
                const float f  = 1.f / (1.f + __expf(-pf));
                float hn = f * hprev + (1.f - f) * tanhf(ph);
                hn = (hn >= 0.f) ? hn : a * hn;
                __stcg(&Hout[(size_t)t * H + myc], hn);
                hprev = hn;
                if (t + 1 < T) {   // prefetch next step's input projections
                    xf_c = __ldg(&xf[(size_t)(t + 1) * H + myc]);
                    xh_c = __ldg(&xh[(size_t)(t + 1) * H + myc]);
                }
            }
            __threadfence();       // publish h_t slice (one warp-level MEMBAR)
            if (lane == 0) {
                atomicAdd(&ctr[t], 1);
                volatile int* p = ctr + t;
                while (*p < NCTA) { }
                __threadfence();   // acquire
            }
        }
        __syncthreads();
    }
}

// ---------------------------------------------------------------------------
// block reduce helper (256 threads)
// ---------------------------------------------------------------------------
__device__ __forceinline__ float block_sum_256(float v) {
    __shared__ float sh[8];
    const int tid = threadIdx.x;
    #pragma unroll
    for (int s = 16; s; s >>= 1) v += __shfl_xor_sync(0xffffffffu, v, s);
    if ((tid & 31) == 0) sh[tid >> 5] = v;
    __syncthreads();
    if (tid == 0) {
        float r = 0.f;
        #pragma unroll
        for (int i = 0; i < 8; i++) r += sh[i];
        sh[0] = r;
    }
    __syncthreads();
    const float r = sh[0];
    __syncthreads();
    return r;
}

// ---------------------------------------------------------------------------
// LayerNorm (torch-style: unbiased std). 1 row/block.
// ---------------------------------------------------------------------------
__global__ __launch_bounds__(256) void layernorm_kernel(
    const float* __restrict__ X, const float* __restrict__ ga,
    const float* __restrict__ be, float* __restrict__ Y)
{
    const int H = H_DIM;
    const int row = blockIdx.x;
    const int tid = threadIdx.x;
    const float* x = X + (size_t)row * H;
    float xr[8];
    #pragma unroll
    for (int j = 0; j < 8; j++) xr[j] = x[tid + 256 * j];

    float s = 0.f;
    #pragma unroll
    for (int j = 0; j < 8; j++) s += xr[j];
    const float mean = block_sum_256(s) * (1.f / H);

    float sq = 0.f;
    #pragma unroll
    for (int j = 0; j < 8; j++) { const float d = xr[j] - mean; sq += d * d; }
    const float var = block_sum_256(sq) * (1.f / (H - 1));
    const float inv = 1.f / (sqrtf(var) + EPS);

    float* y = Y + (size_t)row * H;
    #pragma unroll
    for (int j = 0; j < 8; j++) {
        const int k = tid + 256 * j;
        y[k] = ga[k] * (xr[j] - mean) * inv + be[k];
    }
}

// ---------------------------------------------------------------------------
// Fused head: LN(layer1 h) @ W_out + b_out -> log_softmax.  1 row/block.
// ---------------------------------------------------------------------------
__global__ __launch_bounds__(256) void head_kernel(
    const float* __restrict__ Hin, const float* __restrict__ ga,
    const float* __restrict__ be, const float* __restrict__ Wout,
    const float* __restrict__ bout, float* __restrict__ out)
{
    const int H = H_DIM;
    const int row = blockIdx.x;
    const int tid = threadIdx.x;
    const float* x = Hin + (size_t)row * H;

    float xr[8];
    #pragma unroll
    for (int j = 0; j < 8; j++) xr[j] = x[tid + 256 * j];

    float s = 0.f;
    #pragma unroll
    for (int j = 0; j < 8; j++) s += xr[j];
    const float mean = block_sum_256(s) * (1.f / H);

    float sq = 0.f;
    #pragma unroll
    for (int j = 0; j < 8; j++) { const float d = xr[j] - mean; sq += d * d; }
    const float var = block_sum_256(sq) * (1.f / (H - 1));
    const float inv = 1.f / (sqrtf(var) + EPS);

    float acc[OUT_DIM];
    #pragma unroll
    for (int o = 0; o < OUT_DIM; o++) acc[o] = 0.f;
    #pragma unroll
    for (int j = 0; j < 8; j++) {
        const int k = tid + 256 * j;
        const float xn = ga[k] * (xr[j] - mean) * inv + be[k];
        #pragma unroll
        for (int o = 0; o < OUT_DIM; o++)
            acc[o] = fmaf(xn, Wout[k * OUT_DIM + o], acc[o]);
    }

    __shared__ float wred[8][OUT_DIM];
    #pragma unroll
    for (int o = 0; o < OUT_DIM; o++) {
        float v = acc[o];
        #pragma unroll
        for (int st = 16; st; st >>= 1) v += __shfl_xor_sync(0xffffffffu, v, st);
        if ((tid & 31) == 0) wred[tid >> 5][o] = v;
    }
    __syncthreads();
    if (tid == 0) {
        float logits[OUT_DIM];
        #pragma unroll
        for (int o = 0; o < OUT_DIM; o++) {
            float v = bout[o];
            #pragma unroll
            for (int w = 0; w < 8; w++) v += wred[w][o];
            logits[o] = v;
        }
        float mx = logits[0];
        #pragma unroll
        for (int o = 1; o < OUT_DIM; o++) mx = fmaxf(mx, logits[o]);
        float se = 0.f;
        #pragma unroll
        for (int o = 0; o < OUT_DIM; o++) se += expf(logits[o] - mx);
        const float lse = mx + logf(se);
        #pragma unroll
        for (int o = 0; o < OUT_DIM; o++)
            out[(size_t)row * OUT_DIM + o] = logits[o] - lse;
    }
}

// ---------------------------------------------------------------------------
// Launch
// ---------------------------------------------------------------------------
extern "C" void kernel_launch(void* const* d_in, const int* in_sizes, int n_in,
                              void* d_out, int out_size)
{
    const float* x     = (const float*)d_in[0];
    const float* W_f0  = (const float*)d_in[1];
    const float* U_f0  = (const float*)d_in[2];
    const float* b_f0  = (const float*)d_in[3];
    const float* W_h0  = (const float*)d_in[4];
    const float* U_h0  = (const float*)d_in[5];
    const float* b_h0  = (const float*)d_in[6];
    const float* pr0   = (const float*)d_in[7];
    const float* ga0   = (const float*)d_in[8];
    const float* be0   = (const float*)d_in[9];
    const float* W_f1  = (const float*)d_in[10];
    const float* U_f1  = (const float*)d_in[11];
    const float* b_f1  = (const float*)d_in[12];
    const float* W_h1  = (const float*)d_in[13];
    const float* U_h1  = (const float*)d_in[14];
    const float* b_h1  = (const float*)d_in[15];
    const float* pr1   = (const float*)d_in[16];
    const float* ga1   = (const float*)d_in[17];
    const float* be1   = (const float*)d_in[18];
    const float* W_out = (const float*)d_in[19];
    const float* b_out = (const float*)d_in[20];
    float* out = (float*)d_out;

    const int H = H_DIM;
    const int T = in_sizes[0] / 2048;   // 4096

    float *p_xf, *p_xh, *p_h, *p_hn;
    int* p_ctr;
    cudaGetSymbolAddress((void**)&p_xf, g_xf);
    cudaGetSymbolAddress((void**)&p_xh, g_xh);
    cudaGetSymbolAddress((void**)&p_h,  g_h);
    cudaGetSymbolAddress((void**)&p_hn, g_hn);
    cudaGetSymbolAddress((void**)&p_ctr, g_ctr);

    // dyn smem: weights half (128KB) + h row (8KB) + partials (2KB)
    const int scan_smem = (16 * 64 * 32 + H + 16 * 32) * (int)sizeof(float);
    cudaFuncSetAttribute(janet_scan_kernel,
                         cudaFuncAttributeMaxDynamicSharedMemorySize, scan_smem);

    dim3 ggrid(H / BN, T / BM, 2);   // (16, 32, 2): f and h GEMMs fused

    // ---- layer 0 ----
    cudaMemsetAsync(p_ctr, 0, T * sizeof(int));
    sgemm_bias2_kernel<<<ggrid, 256>>>(x, W_f0, b_f0, p_xf, W_h0, b_h0, p_xh, T, H, H);
    janet_scan_kernel<<<NCTA, SCAN_THREADS, scan_smem>>>(
        U_f0, U_h0, p_xf, p_xh, p_h, pr0, p_ctr, T);
    layernorm_kernel<<<T, 256>>>(p_h, ga0, be0, p_hn);

    // ---- layer 1 ----
    cudaMemsetAsync(p_ctr, 0, T * sizeof(int));
    sgemm_bias2_kernel<<<ggrid, 256>>>(p_hn, W_f1, b_f1, p_xf, W_h1, b_h1, p_xh, T, H, H);
    janet_scan_kernel<<<NCTA, SCAN_THREADS, scan_smem>>>(
        U_f1, U_h1, p_xf, p_xh, p_h, pr1, p_ctr, T);

    // ---- LN1 + head + log_softmax ----
    head_kernel<<<T, 256>>>(p_h, ga1, be1, W_out, b_out, out);
}

// round 5
// speedup vs baseline: 1.8194x; 1.0645x over previous
#include <cuda_runtime.h>
#include <cuda_bf16.h>
#include <math.h>

// ---------------------------------------------------------------------------
// Problem constants
// ---------------------------------------------------------------------------
#define T_MAX 4096
#define H_DIM 2048
#define OUT_DIM 10
#define NCTA 148
#define SCAN_THREADS 512
#define EPS 1e-6f

typedef unsigned long long ull;

// packed fp32x2 helpers (PTX ISA 8.7+, sm_100+)
__device__ __forceinline__ void fma2(ull& acc, ull a, ull b) {
    asm("fma.rn.f32x2 %0, %1, %2, %0;" : "+l"(acc) : "l"(a), "l"(b));
}
__device__ __forceinline__ ull pack2(float x, float y) {
    ull r; asm("mov.b64 %0, {%1, %2};" : "=l"(r) : "f"(x), "f"(y)); return r;
}
__device__ __forceinline__ ull dup2(float x) {
    ull r; asm("mov.b64 %0, {%1, %1};" : "=l"(r) : "f"(x)); return r;
}
__device__ __forceinline__ float2 unpack2(ull p) {
    float2 f; asm("mov.b64 {%0, %1}, %2;" : "=f"(f.x), "=f"(f.y) : "l"(p)); return f;
}

// scratch (device globals: allocation-free)
__device__ float g_xf[T_MAX * H_DIM];   // x @ W_f + b_f
__device__ float g_xh[T_MAX * H_DIM];   // x @ W_h + b_h
__device__ float g_h [T_MAX * H_DIM];   // scan output
__device__ float g_hn[T_MAX * H_DIM];   // layernorm output (layer 0)
__device__ int   g_ctr[T_MAX];          // per-step barrier counters

// ---------------------------------------------------------------------------
// SGEMM with bias, fused pair, packed f32x2 accumulation.
// C{f,h}[M,N] = A[M,K] @ B{f,h}[K,N] + bias{f,h}; z selects f/h.
// 128x128 tile, BK=8, 256 threads, 8x8 microtile (acc as 8x4 f32x2).
// ---------------------------------------------------------------------------
#define BM 128
#define BN 128
#define BK 8
#define TM 8
#define TN 8

__global__ __launch_bounds__(256) void sgemm_bias2_kernel(
    const float* __restrict__ A,
    const float* __restrict__ Bf, const float* __restrict__ biasf, float* __restrict__ Cf,
    const float* __restrict__ Bh, const float* __restrict__ biash, float* __restrict__ Ch,
    int M, int N, int K)
{
    __shared__ float As[BK][BM];
    __shared__ float Bs[BK][BN];

    const float* B    = (blockIdx.z == 0) ? Bf : Bh;
    const float* bias = (blockIdx.z == 0) ? biasf : biash;
    float*       C    = (blockIdx.z == 0) ? Cf : Ch;

    const int bx = blockIdx.x;   // N tile
    const int by = blockIdx.y;   // M tile
    const int tid = threadIdx.x;

    const int aRow = tid >> 1;          // 0..127
    const int aCol = (tid & 1) * 4;     // 0 or 4
    const int bRow = tid >> 5;          // 0..7
    const int bCol = (tid & 31) * 4;    // 0..124

    const int tRow = (tid >> 4) * TM;   // 0..120
    const int tCol = (tid & 15) * TN;   // 0..120

    const float* Aptr = A + (size_t)(by * BM) * K;
    const float* Bptr = B + bx * BN;

    ull accp[TM][4];
    #pragma unroll
    for (int i = 0; i < TM; i++)
        #pragma unroll
        for (int j = 0; j < 4; j++) accp[i][j] = 0ULL;

    for (int k0 = 0; k0 < K; k0 += BK) {
        float4 av = *(const float4*)(Aptr + (size_t)aRow * K + k0 + aCol);
        As[aCol + 0][aRow] = av.x;
        As[aCol + 1][aRow] = av.y;
        As[aCol + 2][aRow] = av.z;
        As[aCol + 3][aRow] = av.w;
        float4 bv = *(const float4*)(Bptr + (size_t)(k0 + bRow) * N + bCol);
        *(float4*)&Bs[bRow][bCol] = bv;
        __syncthreads();

        #pragma unroll
        for (int kk = 0; kk < BK; kk++) {
            float4 a0 = *(const float4*)&As[kk][tRow];
            float4 a1 = *(const float4*)&As[kk][tRow + 4];
            float4 b0 = *(const float4*)&Bs[kk][tCol];
            float4 b1 = *(const float4*)&Bs[kk][tCol + 4];
            ull bp[4];
            bp[0] = pack2(b0.x, b0.y);
            bp[1] = pack2(b0.z, b0.w);
            bp[2] = pack2(b1.x, b1.y);
            bp[3] = pack2(b1.z, b1.w);
            float ar[8] = {a0.x, a0.y, a0.z, a0.w, a1.x, a1.y, a1.z, a1.w};
            #pragma unroll
            for (int i = 0; i < TM; i++) {
                ull ad = dup2(ar[i]);
                #pragma unroll
                for (int j = 0; j < 4; j++)
                    fma2(accp[i][j], ad, bp[j]);
            }
        }
        __syncthreads();
    }

    #pragma unroll
    for (int i = 0; i < TM; i++) {
        const int r = by * BM + tRow + i;
        #pragma unroll
        for (int jj = 0; jj < 2; jj++) {
            const int c = bx * BN + tCol + jj * 4;
            float2 e0 = unpack2(accp[i][jj * 2 + 0]);
            float2 e1 = unpack2(accp[i][jj * 2 + 1]);
            float4 v;
            v.x = e0.x + bias[c + 0];
            v.y = e0.y + bias[c + 1];
            v.z = e1.x + bias[c + 2];
            v.w = e1.y + bias[c + 3];
            *(float4*)(C + (size_t)r * N + c) = v;
        }
    }
}

// ---------------------------------------------------------------------------
// Persistent JANET scan, f32x2 packed dots, 96 reg / 32 smem weight split.
// 148 CTAs x 512 threads (16 warps). CTA b owns column pairs [c0, c1), np<=14.
// dot d (d<np: U_f col c0+d; np<=d<2np: U_h col c0+d-np).
// warp w <-> K-chunk [128w, 128w+128); lane <-> dot.
// Lane weights: k-local [0,96) in 48 b64 REGISTERS, [96,128) in smem as
// ulonglong2 ws2[warp][jp(0..7)][lane] (LDS.128, conflict-free).
// h_{t-1} staged once into smem, read as ulonglong2 broadcasts.
// ---------------------------------------------------------------------------
__global__ __launch_bounds__(SCAN_THREADS, 1) void janet_scan_kernel(
    const float* __restrict__ Uf, const float* __restrict__ Uh,
    const float* __restrict__ xf, const float* __restrict__ xh,
    float* __restrict__ Hout, const float* __restrict__ prelu_a,
    int* __restrict__ ctr, int T)
{
    extern __shared__ float smem[];
    const int H = H_DIM;
    ulonglong2* ws2 = (ulonglong2*)smem;      // 16 warps * 8 * 32 * 16B = 64KB
    float* hsm  = smem + (64 * 1024 / 4);     // 2048 floats (8KB)
    float* part = hsm + H;                    // 512 floats (2KB)

    const int b = blockIdx.x;
    const int c0 = (b * H) / NCTA;
    const int c1 = ((b + 1) * H) / NCTA;
    const int np = c1 - c0;          // 13 or 14 column pairs
    const int nd = 2 * np;

    const int tid  = threadIdx.x;
    const int lane = tid & 31;
    const int warp = tid >> 5;
    const float a = *prelu_a;

    // ---- load this lane's weights ----
    const bool valid = lane < nd;
    const int col = c0 + (lane < np ? lane : (valid ? lane - np : 0));
    const float* U = (lane < np) ? Uf : Uh;
    const int kbase = warp * 128;

    ull wr[48];                       // 96 floats in regs
    #pragma unroll
    for (int i = 0; i < 48; i++) {
        const float w0 = valid ? U[(size_t)(kbase + 2 * i + 0) * H + col] : 0.f;
        const float w1 = valid ? U[(size_t)(kbase + 2 * i + 1) * H + col] : 0.f;
        wr[i] = pack2(w0, w1);
    }
    #pragma unroll
    for (int jp = 0; jp < 8; jp++) {  // 32 floats in smem
        const int kk = kbase + 96 + 4 * jp;
        const float w0 = valid ? U[(size_t)(kk + 0) * H + col] : 0.f;
        const float w1 = valid ? U[(size_t)(kk + 1) * H + col] : 0.f;
        const float w2 = valid ? U[(size_t)(kk + 2) * H + col] : 0.f;
        const float w3 = valid ? U[(size_t)(kk + 3) * H + col] : 0.f;
        ulonglong2 wv; wv.x = pack2(w0, w1); wv.y = pack2(w2, w3);
        ws2[warp * 256 + jp * 32 + lane] = wv;
    }

    // per-dot thread state (warp 0, lane < np drives the gate math)
    float hprev = 0.f, xf_c = 0.f, xh_c = 0.f;
    const int myc = c0 + lane;
    if (warp == 0 && lane < np) {
        xf_c = __ldg(&xf[myc]);
        xh_c = __ldg(&xh[myc]);
    }
    __syncthreads();

    float4* hsm4 = (float4*)hsm;
    const ulonglong2* hp  = (const ulonglong2*)(hsm + warp * 128);  // 32 entries
    const ulonglong2* wsp = ws2 + warp * 256 + lane;

    for (int t = 0; t < T; t++) {
        // ---- stage h_{t-1} into smem (one cooperative 8KB load) ----
        if (t == 0) {
            hsm4[tid] = make_float4(0.f, 0.f, 0.f, 0.f);
        } else {
            hsm4[tid] = __ldcg(((const float4*)(Hout + (size_t)(t - 1) * H)) + tid);
        }
        __syncthreads();

        // ---- packed partial dot over this warp's k-chunk ----
        ull a0 = 0ULL, a1 = 0ULL;
        #pragma unroll
        for (int j = 0; j < 24; j++) {          // register half: k [0,96)
            ulonglong2 hv = hp[j];
            fma2(a0, hv.x, wr[2 * j + 0]);
            fma2(a1, hv.y, wr[2 * j + 1]);
        }
        #pragma unroll
        for (int jp = 0; jp < 8; jp++) {        // smem half: k [96,128)
            ulonglong2 hv = hp[24 + jp];
            ulonglong2 wv = wsp[jp * 32];
            fma2(a0, hv.x, wv.x);
            fma2(a1, hv.y, wv.y);
        }
        const float2 f0 = unpack2(a0);
        const float2 f1 = unpack2(a1);
        part[warp * 32 + lane] = (f0.x + f0.y) + (f1.x + f1.y);
        __syncthreads();

        // ---- warp 0: reduce partials, gate, publish, grid barrier ----
        if (warp == 0) {
            float s = 0.f;
            #pragma unroll
            for (int w = 0; w < 16; w++) s += part[w * 32 + lane];
            const float partner = __shfl_sync(0xffffffffu, s, lane + np);
            if (lane < np) {
                const float pf = s + xf_c;
                const float ph = partner + xh_c;
                const float f  = 1.f / (1.f + __expf(-pf));
                float hn = f * hprev + (1.f - f) * tanhf(ph);
                hn = (hn >= 0.f) ? hn : a * hn;
                __stcg(&Hout[(size_t)t * H + myc], hn);
                hprev = hn;
                if (t + 1 < T) {
                    xf_c = __ldg(&xf[(size_t)(t + 1) * H + myc]);
                    xh_c = __ldg(&xh[(size_t)(t + 1) * H + myc]);
                }
            }
            __threadfence();       // publish h_t slice
            if (lane == 0) {
                atomicAdd(&ctr[t], 1);
                volatile int* p = ctr + t;
                while (*p < NCTA) { }
                __threadfence();   // acquire
            }
        }
        __syncthreads();
    }
}

// ---------------------------------------------------------------------------
// block reduce helper (256 threads)
// ---------------------------------------------------------------------------
__device__ __forceinline__ float block_sum_256(float v) {
    __shared__ float sh[8];
    const int tid = threadIdx.x;
    #pragma unroll
    for (int s = 16; s; s >>= 1) v += __shfl_xor_sync(0xffffffffu, v, s);
    if ((tid & 31) == 0) sh[tid >> 5] = v;
    __syncthreads();
    if (tid == 0) {
        float r = 0.f;
        #pragma unroll
        for (int i = 0; i < 8; i++) r += sh[i];
        sh[0] = r;
    }
    __syncthreads();
    const float r = sh[0];
    __syncthreads();
    return r;
}

// ---------------------------------------------------------------------------
// LayerNorm (torch-style: unbiased std). 1 row/block.
// ---------------------------------------------------------------------------
__global__ __launch_bounds__(256) void layernorm_kernel(
    const float* __restrict__ X, const float* __restrict__ ga,
    const float* __restrict__ be, float* __restrict__ Y)
{
    const int H = H_DIM;
    const int row = blockIdx.x;
    const int tid = threadIdx.x;
    const float* x = X + (size_t)row * H;
    float xr[8];
    #pragma unroll
    for (int j = 0; j < 8; j++) xr[j] = x[tid + 256 * j];

    float s = 0.f;
    #pragma unroll
    for (int j = 0; j < 8; j++) s += xr[j];
    const float mean = block_sum_256(s) * (1.f / H);

    float sq = 0.f;
    #pragma unroll
    for (int j = 0; j < 8; j++) { const float d = xr[j] - mean; sq += d * d; }
    const float var = block_sum_256(sq) * (1.f / (H - 1));
    const float inv = 1.f / (sqrtf(var) + EPS);

    float* y = Y + (size_t)row * H;
    #pragma unroll
    for (int j = 0; j < 8; j++) {
        const int k = tid + 256 * j;
        y[k] = ga[k] * (xr[j] - mean) * inv + be[k];
    }
}

// ---------------------------------------------------------------------------
// Fused head: LN(layer1 h) @ W_out + b_out -> log_softmax.  1 row/block.
// ---------------------------------------------------------------------------
__global__ __launch_bounds__(256) void head_kernel(
    const float* __restrict__ Hin, const float* __restrict__ ga,
    const float* __restrict__ be, const float* __restrict__ Wout,
    const float* __restrict__ bout, float* __restrict__ out)
{
    const int H = H_DIM;
    const int row = blockIdx.x;
    const int tid = threadIdx.x;
    const float* x = Hin + (size_t)row * H;

    float xr[8];
    #pragma unroll
    for (int j = 0; j < 8; j++) xr[j] = x[tid + 256 * j];

    float s = 0.f;
    #pragma unroll
    for (int j = 0; j < 8; j++) s += xr[j];
    const float mean = block_sum_256(s) * (1.f / H);

    float sq = 0.f;
    #pragma unroll
    for (int j = 0; j < 8; j++) { const float d = xr[j] - mean; sq += d * d; }
    const float var = block_sum_256(sq) * (1.f / (H - 1));
    const float inv = 1.f / (sqrtf(var) + EPS);

    float acc[OUT_DIM];
    #pragma unroll
    for (int o = 0; o < OUT_DIM; o++) acc[o] = 0.f;
    #pragma unroll
    for (int j = 0; j < 8; j++) {
        const int k = tid + 256 * j;
        const float xn = ga[k] * (xr[j] - mean) * inv + be[k];
        #pragma unroll
        for (int o = 0; o < OUT_DIM; o++)
            acc[o] = fmaf(xn, Wout[k * OUT_DIM + o], acc[o]);
    }

    __shared__ float wred[8][OUT_DIM];
    #pragma unroll
    for (int o = 0; o < OUT_DIM; o++) {
        float v = acc[o];
        #pragma unroll
        for (int st = 16; st; st >>= 1) v += __shfl_xor_sync(0xffffffffu, v, st);
        if ((tid & 31) == 0) wred[tid >> 5][o] = v;
    }
    __syncthreads();
    if (tid == 0) {
        float logits[OUT_DIM];
        #pragma unroll
        for (int o = 0; o < OUT_DIM; o++) {
            float v = bout[o];
            #pragma unroll
            for (int w = 0; w < 8; w++) v += wred[w][o];
            logits[o] = v;
        }
        float mx = logits[0];
        #pragma unroll
        for (int o = 1; o < OUT_DIM; o++) mx = fmaxf(mx, logits[o]);
        float se = 0.f;
        #pragma unroll
        for (int o = 0; o < OUT_DIM; o++) se += expf(logits[o] - mx);
        const float lse = mx + logf(se);
        #pragma unroll
        for (int o = 0; o < OUT_DIM; o++)
            out[(size_t)row * OUT_DIM + o] = logits[o] - lse;
    }
}

// ---------------------------------------------------------------------------
// Launch
// ---------------------------------------------------------------------------
extern "C" void kernel_launch(void* const* d_in, const int* in_sizes, int n_in,
                              void* d_out, int out_size)
{
    const float* x     = (const float*)d_in[0];
    const float* W_f0  = (const float*)d_in[1];
    const float* U_f0  = (const float*)d_in[2];
    const float* b_f0  = (const float*)d_in[3];
    const float* W_h0  = (const float*)d_in[4];
    const float* U_h0  = (const float*)d_in[5];
    const float* b_h0  = (const float*)d_in[6];
    const float* pr0   = (const float*)d_in[7];
    const float* ga0   = (const float*)d_in[8];
    const float* be0   = (const float*)d_in[9];
    const float* W_f1  = (const float*)d_in[10];
    const float* U_f1  = (const float*)d_in[11];
    const float* b_f1  = (const float*)d_in[12];
    const float* W_h1  = (const float*)d_in[13];
    const float* U_h1  = (const float*)d_in[14];
    const float* b_h1  = (const float*)d_in[15];
    const float* pr1   = (const float*)d_in[16];
    const float* ga1   = (const float*)d_in[17];
    const float* be1   = (const float*)d_in[18];
    const float* W_out = (const float*)d_in[19];
    const float* b_out = (const float*)d_in[20];
    float* out = (float*)d_out;

    const int H = H_DIM;
    const int T = in_sizes[0] / 2048;   // 4096

    float *p_xf, *p_xh, *p_h, *p_hn;
    int* p_ctr;
    cudaGetSymbolAddress((void**)&p_xf, g_xf);
    cudaGetSymbolAddress((void**)&p_xh, g_xh);
    cudaGetSymbolAddress((void**)&p_h,  g_h);
    cudaGetSymbolAddress((void**)&p_hn, g_hn);
    cudaGetSymbolAddress((void**)&p_ctr, g_ctr);

    // actual use: 64KB weights + 8KB h + 2KB partials = 74KB.
    // Request 136KB to hard-force 1 CTA/SM (barrier safety: grid==148==#SMs).
    const int scan_smem = 136 * 1024;
    cudaFuncSetAttribute(janet_scan_kernel,
                         cudaFuncAttributeMaxDynamicSharedMemorySize, scan_smem);

    dim3 ggrid(H / BN, T / BM, 2);   // (16, 32, 2): f and h GEMMs fused

    // ---- layer 0 ----
    cudaMemsetAsync(p_ctr, 0, T * sizeof(int));
    sgemm_bias2_kernel<<<ggrid, 256>>>(x, W_f0, b_f0, p_xf, W_h0, b_h0, p_xh, T, H, H);
    janet_scan_kernel<<<NCTA, SCAN_THREADS, scan_smem>>>(
        U_f0, U_h0, p_xf, p_xh, p_h, pr0, p_ctr, T);
    layernorm_kernel<<<T, 256>>>(p_h, ga0, be0, p_hn);

    // ---- layer 1 ----
    cudaMemsetAsync(p_ctr, 0, T * sizeof(int));
    sgemm_bias2_kernel<<<ggrid, 256>>>(p_hn, W_f1, b_f1, p_xf, W_h1, b_h1, p_xh, T, H, H);
    janet_scan_kernel<<<NCTA, SCAN_THREADS, scan_smem>>>(
        U_f1, U_h1, p_xf, p_xh, p_h, pr1, p_ctr, T);

    // ---- LN1 + head + log_softmax ----
    head_kernel<<<T, 256>>>(p_h, ga1, be1, W_out, b_out, out);
}

// round 6
// speedup vs baseline: 1.9894x; 1.0934x over previous
#include <cuda_runtime.h>
#include <cuda_bf16.h>
#include <math.h>

// ---------------------------------------------------------------------------
// Problem constants
// ---------------------------------------------------------------------------
#define T_MAX 4096
#define H_DIM 2048
#define OUT_DIM 10
#define NCTA 148
#define SCAN_THREADS 512
#define EPS 1e-6f

typedef unsigned long long ull;

// packed fp32x2 helpers (PTX ISA 8.7+, sm_100+)
__device__ __forceinline__ void fma2(ull& acc, ull a, ull b) {
    asm("fma.rn.f32x2 %0, %1, %2, %0;" : "+l"(acc) : "l"(a), "l"(b));
}
__device__ __forceinline__ ull pack2(float x, float y) {
    ull r; asm("mov.b64 %0, {%1, %2};" : "=l"(r) : "f"(x), "f"(y)); return r;
}
__device__ __forceinline__ float2 unpack2(ull p) {
    float2 f; asm("mov.b64 {%0, %1}, %2;" : "=f"(f.x), "=f"(f.y) : "l"(p)); return f;
}

// tf32 helpers
__device__ __forceinline__ float totf32(float x) {
    float r; asm("cvt.rna.tf32.f32 %0, %1;" : "=f"(r) : "f"(x)); return r;
}
__device__ __forceinline__ void mma_tf32(float* c, const float* a, const float* b) {
    asm("mma.sync.aligned.m16n8k8.row.col.f32.tf32.tf32.f32 "
        "{%0,%1,%2,%3}, {%4,%5,%6,%7}, {%8,%9}, {%0,%1,%2,%3};"
        : "+f"(c[0]), "+f"(c[1]), "+f"(c[2]), "+f"(c[3])
        : "f"(a[0]), "f"(a[1]), "f"(a[2]), "f"(a[3]), "f"(b[0]), "f"(b[1]));
}

// scratch (device globals: allocation-free)
__device__ float g_xf[T_MAX * H_DIM];   // x @ W_f + b_f
__device__ float g_xh[T_MAX * H_DIM];   // x @ W_h + b_h
__device__ float g_h [T_MAX * H_DIM];   // scan output
__device__ float g_hn[T_MAX * H_DIM];   // layernorm output (layer 0)
__device__ int   g_ctr[T_MAX];          // per-step barrier counters

// ---------------------------------------------------------------------------
// TF32 tensor-core GEMM with bias, fused f/h pair (blockIdx.z selects).
// C[M,N] = A[M,K] @ B[K,N] + bias[N], fp32 in/out, tf32 mma, fp32 accum.
// 128x128x32 CTA tile, 256 threads = 8 warps (2m x 4n), warp tile 64x32,
// mma.m16n8k8: per warp 4 m-tiles x 4 n-tiles.
// As: [m][k] stride 36 (frag loads bank-conflict-free: 4g+tg distinct mod 32)
// Bs: [k][n] stride 136 (8tg+g distinct mod 32). Staging via STS.128.
// ---------------------------------------------------------------------------
#define GBK 32
#define AS_STR 36
#define BS_STR 136

__global__ __launch_bounds__(256) void tf32_gemm_bias2_kernel(
    const float* __restrict__ A,
    const float* __restrict__ Bf, const float* __restrict__ biasf, float* __restrict__ Cf,
    const float* __restrict__ Bh, const float* __restrict__ biash, float* __restrict__ Ch,
    int M, int N, int K)
{
    __shared__ float As[128 * AS_STR];
    __shared__ float Bs[GBK * BS_STR];

    const float* B    = blockIdx.z ? Bh : Bf;
    const float* bias = blockIdx.z ? biash : biasf;
    float*       C    = blockIdx.z ? Ch : Cf;

    const int tid  = threadIdx.x;
    const int warp = tid >> 5;
    const int lane = tid & 31;
    const int g    = lane >> 2;        // groupID 0..7
    const int tg   = lane & 3;         // thread-in-group 0..3

    const int wm = (warp >> 2) * 64;   // warp m offset: 0 or 64
    const int wn = (warp & 3) * 32;    // warp n offset: 0..96

    // staging index split
    const int ar  = tid >> 3;          // A rows ar + 32*i
    const int ac4 = (tid & 7) * 4;     // A col (float)
    const int br  = tid >> 5;          // B rows br + 8*i
    const int bc4 = (tid & 31) * 4;    // B col (float)

    float acc[4][4][4];
    #pragma unroll
    for (int mt = 0; mt < 4; mt++)
        #pragma unroll
        for (int nt = 0; nt < 4; nt++)
            #pragma unroll
            for (int r = 0; r < 4; r++) acc[mt][nt][r] = 0.f;

    const float* Ap = A + (size_t)(blockIdx.y * 128) * K;
    const float* Bp = B + blockIdx.x * 128;

    for (int kt = 0; kt < K; kt += GBK) {
        // ---- gmem -> regs (coalesced float4), round to tf32 ----
        float4 a4[4], b4[4];
        #pragma unroll
        for (int i = 0; i < 4; i++)
            a4[i] = *(const float4*)(Ap + (size_t)(ar + 32 * i) * K + kt + ac4);
        #pragma unroll
        for (int i = 0; i < 4; i++)
            b4[i] = *(const float4*)(Bp + (size_t)(kt + br + 8 * i) * N + bc4);
        #pragma unroll
        for (int i = 0; i < 4; i++) {
            a4[i].x = totf32(a4[i].x); a4[i].y = totf32(a4[i].y);
            a4[i].z = totf32(a4[i].z); a4[i].w = totf32(a4[i].w);
            b4[i].x = totf32(b4[i].x); b4[i].y = totf32(b4[i].y);
            b4[i].z = totf32(b4[i].z); b4[i].w = totf32(b4[i].w);
        }
        __syncthreads();   // protect previous iteration's smem reads
        #pragma unroll
        for (int i = 0; i < 4; i++)
            *(float4*)&As[(ar + 32 * i) * AS_STR + ac4] = a4[i];
        #pragma unroll
        for (int i = 0; i < 4; i++)
            *(float4*)&Bs[(br + 8 * i) * BS_STR + bc4] = b4[i];
        __syncthreads();

        // ---- 4 k8-steps of mma ----
        #pragma unroll
        for (int ks = 0; ks < 4; ks++) {
            const int kk = ks * 8;
            float af[4][4], bf[4][2];
            #pragma unroll
            for (int mt = 0; mt < 4; mt++) {
                const int m0 = wm + mt * 16;
                af[mt][0] = As[(m0 + g)     * AS_STR + kk + tg];
                af[mt][1] = As[(m0 + g + 8) * AS_STR + kk + tg];
                af[mt][2] = As[(m0 + g)     * AS_STR + kk + tg + 4];
                af[mt][3] = As[(m0 + g + 8) * AS_STR + kk + tg + 4];
            }
            #pragma unroll
            for (int nt = 0; nt < 4; nt++) {
                const int n0 = wn + nt * 8;
                bf[nt][0] = Bs[(kk + tg)     * BS_STR + n0 + g];
                bf[nt][1] = Bs[(kk + tg + 4) * BS_STR + n0 + g];
            }
            #pragma unroll
            for (int mt = 0; mt < 4; mt++)
                #pragma unroll
                for (int nt = 0; nt < 4; nt++)
                    mma_tf32(acc[mt][nt], af[mt], bf[nt]);
        }
    }

    // ---- epilogue: bias + store (STG.64 pairs) ----
    #pragma unroll
    for (int mt = 0; mt < 4; mt++) {
        const int row0 = blockIdx.y * 128 + wm + mt * 16 + g;
        const int row1 = row0 + 8;
        #pragma unroll
        for (int nt = 0; nt < 4; nt++) {
            const int col = blockIdx.x * 128 + wn + nt * 8 + 2 * tg;
            const float b0 = bias[col], b1 = bias[col + 1];
            float2 v0, v1;
            v0.x = acc[mt][nt][0] + b0; v0.y = acc[mt][nt][1] + b1;
            v1.x = acc[mt][nt][2] + b0; v1.y = acc[mt][nt][3] + b1;
            *(float2*)(C + (size_t)row0 * N + col) = v0;
            *(float2*)(C + (size_t)row1 * N + col) = v1;
        }
    }
}

// ---------------------------------------------------------------------------
// Persistent JANET scan, f32x2 packed dots, 96 reg / 32 smem weight split.
// (unchanged from round 5 — see that round's notes)
// ---------------------------------------------------------------------------
__global__ __launch_bounds__(SCAN_THREADS, 1) void janet_scan_kernel(
    const float* __restrict__ Uf, const float* __restrict__ Uh,
    const float* __restrict__ xf, const float* __restrict__ xh,
    float* __restrict__ Hout, const float* __restrict__ prelu_a,
    int* __restrict__ ctr, int T)
{
    extern __shared__ float smem[];
    const int H = H_DIM;
    ulonglong2* ws2 = (ulonglong2*)smem;      // 16 warps * 8 * 32 * 16B = 64KB
    float* hsm  = smem + (64 * 1024 / 4);     // 2048 floats (8KB)
    float* part = hsm + H;                    // 512 floats (2KB)

    const int b = blockIdx.x;
    const int c0 = (b * H) / NCTA;
    const int c1 = ((b + 1) * H) / NCTA;
    const int np = c1 - c0;          // 13 or 14 column pairs
    const int nd = 2 * np;

    const int tid  = threadIdx.x;
    const int lane = tid & 31;
    const int warp = tid >> 5;
    const float a = *prelu_a;

    // ---- load this lane's weights ----
    const bool valid = lane < nd;
    const int col = c0 + (lane < np ? lane : (valid ? lane - np : 0));
    const float* U = (lane < np) ? Uf : Uh;
    const int kbase = warp * 128;

    ull wr[48];                       // 96 floats in regs
    #pragma unroll
    for (int i = 0; i < 48; i++) {
        const float w0 = valid ? U[(size_t)(kbase + 2 * i + 0) * H + col] : 0.f;
        const float w1 = valid ? U[(size_t)(kbase + 2 * i + 1) * H + col] : 0.f;
        wr[i] = pack2(w0, w1);
    }
    #pragma unroll
    for (int jp = 0; jp < 8; jp++) {  // 32 floats in smem
        const int kk = kbase + 96 + 4 * jp;
        const float w0 = valid ? U[(size_t)(kk + 0) * H + col] : 0.f;
        const float w1 = valid ? U[(size_t)(kk + 1) * H + col] : 0.f;
        const float w2 = valid ? U[(size_t)(kk + 2) * H + col] : 0.f;
        const float w3 = valid ? U[(size_t)(kk + 3) * H + col] : 0.f;
        ulonglong2 wv; wv.x = pack2(w0, w1); wv.y = pack2(w2, w3);
        ws2[warp * 256 + jp * 32 + lane] = wv;
    }

    // per-dot thread state (warp 0, lane < np drives the gate math)
    float hprev = 0.f, xf_c = 0.f, xh_c = 0.f;
    const int myc = c0 + lane;
    if (warp == 0 && lane < np) {
        xf_c = __ldg(&xf[myc]);
        xh_c = __ldg(&xh[myc]);
    }
    __syncthreads();

    float4* hsm4 = (float4*)hsm;
    const ulonglong2* hp  = (const ulonglong2*)(hsm + warp * 128);  // 32 entries
    const ulonglong2* wsp = ws2 + warp * 256 + lane;

    for (int t = 0; t < T; t++) {
        // ---- stage h_{t-1} into smem (one cooperative 8KB load) ----
        if (t == 0) {
            hsm4[tid] = make_float4(0.f, 0.f, 0.f, 0.f);
        } else {
            hsm4[tid] = __ldcg(((const float4*)(Hout + (size_t)(t - 1) * H)) + tid);
        }
        __syncthreads();

        // ---- packed partial dot over this warp's k-chunk ----
        ull a0 = 0ULL, a1 = 0ULL;
        #pragma unroll
        for (int j = 0; j < 24; j++) {          // register half: k [0,96)
            ulonglong2 hv = hp[j];
            fma2(a0, hv.x, wr[2 * j + 0]);
            fma2(a1, hv.y, wr[2 * j + 1]);
        }
        #pragma unroll
        for (int jp = 0; jp < 8; jp++) {        // smem half: k [96,128)
            ulonglong2 hv = hp[24 + jp];
            ulonglong2 wv = wsp[jp * 32];
            fma2(a0, hv.x, wv.x);
            fma2(a1, hv.y, wv.y);
        }
        const float2 f0 = unpack2(a0);
        const float2 f1 = unpack2(a1);
        part[warp * 32 + lane] = (f0.x + f0.y) + (f1.x + f1.y);
        __syncthreads();

        // ---- warp 0: reduce partials, gate, publish, grid barrier ----
        if (warp == 0) {
            float s = 0.f;
            #pragma unroll
            for (int w = 0; w < 16; w++) s += part[w * 32 + lane];
            const float partner = __shfl_sync(0xffffffffu, s, lane + np);
            if (lane < np) {
                const float pf = s + xf_c;
                const float ph = partner + xh_c;
                const float f  = 1.f / (1.f + __expf(-pf));
                float hn = f * hprev + (1.f - f) * tanhf(ph);
                hn = (hn >= 0.f) ? hn : a * hn;
                __stcg(&Hout[(size_t)t * H + myc], hn);
                hprev = hn;
                if (t + 1 < T) {
                    xf_c = __ldg(&xf[(size_t)(t + 1) * H + myc]);
                    xh_c = __ldg(&xh[(size_t)(t + 1) * H + myc]);
                }
            }
            __threadfence();       // publish h_t slice
            if (lane == 0) {
                atomicAdd(&ctr[t], 1);
                volatile int* p = ctr + t;
                while (*p < NCTA) { }
                __threadfence();   // acquire
            }
        }
        __syncthreads();
    }
}

// ---------------------------------------------------------------------------
// block reduce helper (256 threads)
// ---------------------------------------------------------------------------
__device__ __forceinline__ float block_sum_256(float v) {
    __shared__ float sh[8];
    const int tid = threadIdx.x;
    #pragma unroll
    for (int s = 16; s; s >>= 1) v += __shfl_xor_sync(0xffffffffu, v, s);
    if ((tid & 31) == 0) sh[tid >> 5] = v;
    __syncthreads();
    if (tid == 0) {
        float r = 0.f;
        #pragma unroll
        for (int i = 0; i < 8; i++) r += sh[i];
        sh[0] = r;
    }
    __syncthreads();
    const float r = sh[0];
    __syncthreads();
    return r;
}

// ---------------------------------------------------------------------------
// LayerNorm (torch-style: unbiased std). 1 row/block.
// ---------------------------------------------------------------------------
__global__ __launch_bounds__(256) void layernorm_kernel(
    const float* __restrict__ X, const float* __restrict__ ga,
    const float* __restrict__ be, float* __restrict__ Y)
{
    const int H = H_DIM;
    const int row = blockIdx.x;
    const int tid = threadIdx.x;
    const float* x = X + (size_t)row * H;
    float xr[8];
    #pragma unroll
    for (int j = 0; j < 8; j++) xr[j] = x[tid + 256 * j];

    float s = 0.f;
    #pragma unroll
    for (int j = 0; j < 8; j++) s += xr[j];
    const float mean = block_sum_256(s) * (1.f / H);

    float sq = 0.f;
    #pragma unroll
    for (int j = 0; j < 8; j++) { const float d = xr[j] - mean; sq += d * d; }
    const float var = block_sum_256(sq) * (1.f / (H - 1));
    const float inv = 1.f / (sqrtf(var) + EPS);

    float* y = Y + (size_t)row * H;
    #pragma unroll
    for (int j = 0; j < 8; j++) {
        const int k = tid + 256 * j;
        y[k] = ga[k] * (xr[j] - mean) * inv + be[k];
    }
}

// ---------------------------------------------------------------------------
// Fused head: LN(layer1 h) @ W_out + b_out -> log_softmax.  1 row/block.
// ---------------------------------------------------------------------------
__global__ __launch_bounds__(256) void head_kernel(
    const float* __restrict__ Hin, const float* __restrict__ ga,
    const float* __restrict__ be, const float* __restrict__ Wout,
    const float* __restrict__ bout, float* __restrict__ out)
{
    const int H = H_DIM;
    const int row = blockIdx.x;
    const int tid = threadIdx.x;
    const float* x = Hin + (size_t)row * H;

    float xr[8];
    #pragma unroll
    for (int j = 0; j < 8; j++) xr[j] = x[tid + 256 * j];

    float s = 0.f;
    #pragma unroll
    for (int j = 0; j < 8; j++) s += xr[j];
    const float mean = block_sum_256(s) * (1.f / H);

    float sq = 0.f;
    #pragma unroll
    for (int j = 0; j < 8; j++) { const float d = xr[j] - mean; sq += d * d; }
    const float var = block_sum_256(sq) * (1.f / (H - 1));
    const float inv = 1.f / (sqrtf(var) + EPS);

    float acc[OUT_DIM];
    #pragma unroll
    for (int o = 0; o < OUT_DIM; o++) acc[o] = 0.f;
    #pragma unroll
    for (int j = 0; j < 8; j++) {
        const int k = tid + 256 * j;
        const float xn = ga[k] * (xr[j] - mean) * inv + be[k];
        #pragma unroll
        for (int o = 0; o < OUT_DIM; o++)
            acc[o] = fmaf(xn, Wout[k * OUT_DIM + o], acc[o]);
    }

    __shared__ float wred[8][OUT_DIM];
    #pragma unroll
    for (int o = 0; o < OUT_DIM; o++) {
        float v = acc[o];
        #pragma unroll
        for (int st = 16; st; st >>= 1) v += __shfl_xor_sync(0xffffffffu, v, st);
        if ((tid & 31) == 0) wred[tid >> 5][o] = v;
    }
    __syncthreads();
    if (tid == 0) {
        float logits[OUT_DIM];
        #pragma unroll
        for (int o = 0; o < OUT_DIM; o++) {
            float v = bout[o];
            #pragma unroll
            for (int w = 0; w < 8; w++) v += wred[w][o];
            logits[o] = v;
        }
        float mx = logits[0];
        #pragma unroll
        for (int o = 1; o < OUT_DIM; o++) mx = fmaxf(mx, logits[o]);
        float se = 0.f;
        #pragma unroll
        for (int o = 0; o < OUT_DIM; o++) se += expf(logits[o] - mx);
        const float lse = mx + logf(se);
        #pragma unroll
        for (int o = 0; o < OUT_DIM; o++)
            out[(size_t)row * OUT_DIM + o] = logits[o] - lse;
    }
}

// ---------------------------------------------------------------------------
// Launch
// ---------------------------------------------------------------------------
extern "C" void kernel_launch(void* const* d_in, const int* in_sizes, int n_in,
                              void* d_out, int out_size)
{
    const float* x     = (const float*)d_in[0];
    const float* W_f0  = (const float*)d_in[1];
    const float* U_f0  = (const float*)d_in[2];
    const float* b_f0  = (const float*)d_in[3];
    const float* W_h0  = (const float*)d_in[4];
    const float* U_h0  = (const float*)d_in[5];
    const float* b_h0  = (const float*)d_in[6];
    const float* pr0   = (const float*)d_in[7];
    const float* ga0   = (const float*)d_in[8];
    const float* be0   = (const float*)d_in[9];
    const float* W_f1  = (const float*)d_in[10];
    const float* U_f1  = (const float*)d_in[11];
    const float* b_f1  = (const float*)d_in[12];
    const float* W_h1  = (const float*)d_in[13];
    const float* U_h1  = (const float*)d_in[14];
    const float* b_h1  = (const float*)d_in[15];
    const float* pr1   = (const float*)d_in[16];
    const float* ga1   = (const float*)d_in[17];
    const float* be1   = (const float*)d_in[18];
    const float* W_out = (const float*)d_in[19];
    const float* b_out = (const float*)d_in[20];
    float* out = (float*)d_out;

    const int H = H_DIM;
    const int T = in_sizes[0] / 2048;   // 4096

    float *p_xf, *p_xh, *p_h, *p_hn;
    int* p_ctr;
    cudaGetSymbolAddress((void**)&p_xf, g_xf);
    cudaGetSymbolAddress((void**)&p_xh, g_xh);
    cudaGetSymbolAddress((void**)&p_h,  g_h);
    cudaGetSymbolAddress((void**)&p_hn, g_hn);
    cudaGetSymbolAddress((void**)&p_ctr, g_ctr);

    // actual use: 64KB weights + 8KB h + 2KB partials = 74KB.
    // Request 136KB to hard-force 1 CTA/SM (barrier safety: grid==148==#SMs).
    const int scan_smem = 136 * 1024;
    cudaFuncSetAttribute(janet_scan_kernel,
                         cudaFuncAttributeMaxDynamicSharedMemorySize, scan_smem);

    dim3 ggrid(H / 128, T / 128, 2);   // (16, 32, 2): f and h GEMMs fused

    // ---- layer 0 ----
    cudaMemsetAsync(p_ctr, 0, T * sizeof(int));
    tf32_gemm_bias2_kernel<<<ggrid, 256>>>(x, W_f0, b_f0, p_xf, W_h0, b_h0, p_xh, T, H, H);
    janet_scan_kernel<<<NCTA, SCAN_THREADS, scan_smem>>>(
        U_f0, U_h0, p_xf, p_xh, p_h, pr0, p_ctr, T);
    layernorm_kernel<<<T, 256>>>(p_h, ga0, be0, p_hn);

    // ---- layer 1 ----
    cudaMemsetAsync(p_ctr, 0, T * sizeof(int));
    tf32_gemm_bias2_kernel<<<ggrid, 256>>>(p_hn, W_f1, b_f1, p_xf, W_h1, b_h1, p_xh, T, H, H);
    janet_scan_kernel<<<NCTA, SCAN_THREADS, scan_smem>>>(
        U_f1, U_h1, p_xf, p_xh, p_h, pr1, p_ctr, T);

    // ---- LN1 + head + log_softmax ----
    head_kernel<<<T, 256>>>(p_h, ga1, be1, W_out, b_out, out);
}